// round 6
// baseline (speedup 1.0000x reference)
#include <cuda_runtime.h>
#include <cstdint>

// HadamardTransform: y[b,:,h,w] = (H_1024 @ pad(x[b,:,h,w]))[0:768] / 32
// Persistent CTAs + atomic tile queue. FWHT-1024 as two packed-f32x2 passes:
//   pass1 over c_hi (24 live u64 via radix-8 x3 + recombine), smem transpose,
//   pass2 over c_lo (full radix-32), direct streaming gmem I/O.

#define DIMC          768
#define TILE          16
#define THREADS       256
#define PIX_PER_IMG   3136
#define TILES_PER_IMG 196
#define NTILES        3136      // 16 images * 196
#define GRID          592      // 148 SMs * 4 CTAs

__device__ unsigned g_ctr;

__global__ void init_ctr_kernel() { g_ctr = GRID; }

// ---- packed f32x2 ops (sm_103a) ----
__device__ __forceinline__ uint64_t addx2(uint64_t a, uint64_t b) {
    uint64_t d; asm("add.rn.f32x2 %0, %1, %2;" : "=l"(d) : "l"(a), "l"(b)); return d;
}
__device__ __forceinline__ uint64_t subx2(uint64_t a, uint64_t b) {
    const uint64_t NEG1 = 0xBF800000BF800000ULL;
    uint64_t d; asm("fma.rn.f32x2 %0, %1, %2, %3;" : "=l"(d) : "l"(b), "l"(NEG1), "l"(a)); return d;
}
__device__ __forceinline__ uint64_t mulx2(uint64_t a, uint64_t b) {
    uint64_t d; asm("mul.rn.f32x2 %0, %1, %2;" : "=l"(d) : "l"(a), "l"(b)); return d;
}

// 8-point FWHT in place (stages m=1,2,4)
__device__ __forceinline__ void fwht8(uint64_t (&u)[8]) {
    #pragma unroll
    for (int st = 0; st < 3; st++) {
        const int m = 1 << st;
        #pragma unroll
        for (int j = 0; j < 8; j++) {
            if (!(j & m)) {
                uint64_t a = u[j], b = u[j + m];
                u[j]     = addx2(a, b);
                u[j + m] = subx2(a, b);
            }
        }
    }
}

__global__ __launch_bounds__(THREADS, 4)
void fwht1024_kernel(const float* __restrict__ x, float* __restrict__ y) {
    extern __shared__ uint64_t s[];   // 792*8 u64 = 50688 B
    __shared__ unsigned s_tile;

    const int tid = threadIdx.x;
    const int p2  = tid & 7;        // pixel pair -> pixels 2*p2, 2*p2+1
    const int g   = tid >> 3;       // 0..31

    unsigned t = blockIdx.x;        // first tile: static

    while (true) {
        const int b  = t / TILES_PER_IMG;
        const int p0 = (t % TILES_PER_IMG) * TILE;
        const size_t base = (size_t)b * DIMC * PIX_PER_IMG + p0 + 2 * p2;

        // ---- Pass 1: FWHT32 over c_hi (inputs j<24, outputs k_hi<24) ----
        // Decompose: three radix-8 blocks a(j0..7), b(j8..15), c(j16..23);
        // A=a'+b', B=a'-b'; out[0..7]=A+c', out[8..15]=B+c', out[16..23]=A-c'.
        {
            uint64_t va[8], vb[8], vc[8];
            #pragma unroll
            for (int i = 0; i < 8; i++) {
                float2 v0 = __ldg((const float2*)(x + base + (size_t)(( i      ) * 32 + g) * PIX_PER_IMG));
                float2 v1 = __ldg((const float2*)(x + base + (size_t)(( i + 8  ) * 32 + g) * PIX_PER_IMG));
                float2 v2 = __ldg((const float2*)(x + base + (size_t)(( i + 16 ) * 32 + g) * PIX_PER_IMG));
                asm("mov.b64 %0, {%1, %2};" : "=l"(va[i]) : "f"(v0.x), "f"(v0.y));
                asm("mov.b64 %0, {%1, %2};" : "=l"(vb[i]) : "f"(v1.x), "f"(v1.y));
                asm("mov.b64 %0, {%1, %2};" : "=l"(vc[i]) : "f"(v2.x), "f"(v2.y));
            }
            fwht8(va); fwht8(vb); fwht8(vc);

            #pragma unroll
            for (int i = 0; i < 8; i++) {
                uint64_t A = addx2(va[i], vb[i]);
                uint64_t B = subx2(va[i], vb[i]);
                s[(( i      ) * 33 + g) * 8 + p2] = addx2(A, vc[i]);
                s[(( i + 8  ) * 33 + g) * 8 + p2] = addx2(B, vc[i]);
                s[(( i + 16 ) * 33 + g) * 8 + p2] = subx2(A, vc[i]);
            }
        }
        __syncthreads();

        // grab next tile while pass-2 runs (thread g=31 is idle in pass 2)
        if (tid == THREADS - 1)
            s_tile = atomicAdd(&g_ctr, 1u);

        // ---- Pass 2: full FWHT32 over c_lo, direct streaming store ----
        if (g < 24) {
            uint64_t w[32];
            #pragma unroll
            for (int j = 0; j < 32; j++)
                w[j] = s[(g * 33 + j) * 8 + p2];

            #pragma unroll
            for (int st = 0; st < 5; st++) {
                const int m = 1 << st;
                #pragma unroll
                for (int j = 0; j < 32; j++) {
                    if (!(j & m)) {
                        uint64_t a = w[j], c2 = w[j + m];
                        w[j]     = addx2(a, c2);
                        w[j + m] = subx2(a, c2);
                    }
                }
            }

            const uint64_t SCALE = 0x3D0000003D000000ULL;   // (1/32, 1/32)
            #pragma unroll
            for (int j = 0; j < 32; j++) {
                uint64_t r = mulx2(w[j], SCALE);
                float lo, hi;
                asm("mov.b64 {%0, %1}, %2;" : "=f"(lo), "=f"(hi) : "l"(r));
                __stcs((float2*)(y + base + (size_t)(g * 32 + j) * PIX_PER_IMG),
                       make_float2(lo, hi));
            }
        }
        __syncthreads();   // publishes s_tile; also guards smem reuse
        t = s_tile;
        if (t >= NTILES) break;
    }
}

extern "C" void kernel_launch(void* const* d_in, const int* in_sizes, int n_in,
                              void* d_out, int out_size) {
    (void)in_sizes; (void)n_in; (void)out_size;
    const float* x = (const float*)d_in[0];
    float* y = (float*)d_out;

    const int smem_bytes = 792 * 8 * sizeof(uint64_t);   // 50688
    cudaFuncSetAttribute(fwht1024_kernel,
                         cudaFuncAttributeMaxDynamicSharedMemorySize, smem_bytes);

    init_ctr_kernel<<<1, 1>>>();
    fwht1024_kernel<<<GRID, THREADS, smem_bytes>>>(x, y);
}

// round 7
// speedup vs baseline: 1.1897x; 1.1897x over previous
#include <cuda_runtime.h>
#include <cstdint>

// HadamardTransform: y[b,:,h,w] = (H_1024 @ pad(x[b,:,h,w]))[0:768] / 32
// FWHT-1024 per pixel, packed f32x2 (2 pixels/thread), two passes:
//   pass1 over c_hi: radix-8 x3 + recombine (24 live u64), gmem -> smem
//   pass2 over c_lo: stage-16 + two sequential FWHT16 halves (16 live u64),
//                    smem -> gmem directly.
// Low register footprint -> 4 CTAs/SM without spilling.

#define DIMC          768
#define TILE          16
#define THREADS       256
#define PIX_PER_IMG   3136
#define TILES_PER_IMG 196

// ---- packed f32x2 ops (sm_103a) ----
__device__ __forceinline__ uint64_t addx2(uint64_t a, uint64_t b) {
    uint64_t d; asm("add.rn.f32x2 %0, %1, %2;" : "=l"(d) : "l"(a), "l"(b)); return d;
}
__device__ __forceinline__ uint64_t subx2(uint64_t a, uint64_t b) {
    const uint64_t NEG1 = 0xBF800000BF800000ULL;   // (-1.0f, -1.0f)
    uint64_t d; asm("fma.rn.f32x2 %0, %1, %2, %3;" : "=l"(d) : "l"(b), "l"(NEG1), "l"(a)); return d;
}
__device__ __forceinline__ uint64_t mulx2(uint64_t a, uint64_t b) {
    uint64_t d; asm("mul.rn.f32x2 %0, %1, %2;" : "=l"(d) : "l"(a), "l"(b)); return d;
}

// in-place 8-point FWHT
__device__ __forceinline__ void fwht8(uint64_t (&u)[8]) {
    #pragma unroll
    for (int st = 0; st < 3; st++) {
        const int m = 1 << st;
        #pragma unroll
        for (int j = 0; j < 8; j++) {
            if (!(j & m)) {
                uint64_t a = u[j], b = u[j + m];
                u[j]     = addx2(a, b);
                u[j + m] = subx2(a, b);
            }
        }
    }
}

// in-place 16-point FWHT
__device__ __forceinline__ void fwht16(uint64_t (&u)[16]) {
    #pragma unroll
    for (int st = 0; st < 4; st++) {
        const int m = 1 << st;
        #pragma unroll
        for (int j = 0; j < 16; j++) {
            if (!(j & m)) {
                uint64_t a = u[j], b = u[j + m];
                u[j]     = addx2(a, b);
                u[j + m] = subx2(a, b);
            }
        }
    }
}

// smem: row r (0..767) at u64 index (r + (r>>5))*8 + p2 — conflict-free in
// both passes (32-row stride = 528 words == 16 mod 32).

__global__ __launch_bounds__(THREADS, 4)
void fwht1024_kernel(const float* __restrict__ x, float* __restrict__ y) {
    extern __shared__ uint64_t s[];   // 792*8 u64 = 50688 B

    const int tid = threadIdx.x;
    const int T   = blockIdx.x;
    const int b   = T / TILES_PER_IMG;
    const int p0  = (T % TILES_PER_IMG) * TILE;

    const int p2 = tid & 7;        // pixel pair -> pixels 2*p2, 2*p2+1
    const int g  = tid >> 3;       // 0..31

    const size_t base = (size_t)b * DIMC * PIX_PER_IMG + p0 + 2 * p2;

    // ---- Pass 1: FWHT32 over c_hi (24 real inputs, 24 needed outputs) ----
    // blocks a(j=0..7), b(8..15), c(16..23); A=a'+b', B=a'-b';
    // t[0..7]=A+c', t[8..15]=B+c', t[16..23]=A-c'   (j>=24 never read later)
    {
        uint64_t va[8], vb[8], vc[8];
        #pragma unroll
        for (int i = 0; i < 8; i++) {
            float2 v0 = *(const float2*)(x + base + (size_t)((i     ) * 32 + g) * PIX_PER_IMG);
            float2 v1 = *(const float2*)(x + base + (size_t)((i +  8) * 32 + g) * PIX_PER_IMG);
            float2 v2 = *(const float2*)(x + base + (size_t)((i + 16) * 32 + g) * PIX_PER_IMG);
            asm("mov.b64 %0, {%1, %2};" : "=l"(va[i]) : "f"(v0.x), "f"(v0.y));
            asm("mov.b64 %0, {%1, %2};" : "=l"(vb[i]) : "f"(v1.x), "f"(v1.y));
            asm("mov.b64 %0, {%1, %2};" : "=l"(vc[i]) : "f"(v2.x), "f"(v2.y));
        }
        fwht8(va); fwht8(vb); fwht8(vc);

        #pragma unroll
        for (int i = 0; i < 8; i++) {
            uint64_t A = addx2(va[i], vb[i]);
            uint64_t B = subx2(va[i], vb[i]);
            s[((i     ) * 33 + g) * 8 + p2] = addx2(A, vc[i]);
            s[((i +  8) * 33 + g) * 8 + p2] = addx2(B, vc[i]);
            s[((i + 16) * 33 + g) * 8 + p2] = subx2(A, vc[i]);
        }
    }
    __syncthreads();

    // ---- Pass 2: FWHT32 over c_lo = stage m=16, then two FWHT16 halves ----
    if (g < 24) {
        const uint64_t SCALE = 0x3D0000003D000000ULL;   // (1/32, 1/32)
        const uint64_t* sr = s + (size_t)g * 33 * 8 + p2;

        // half A: outputs k = 0..15
        {
            uint64_t u[16];
            #pragma unroll
            for (int j = 0; j < 16; j++)
                u[j] = addx2(sr[(size_t)j * 8], sr[(size_t)(j + 16) * 8]);
            fwht16(u);
            #pragma unroll
            for (int k = 0; k < 16; k++) {
                uint64_t r = mulx2(u[k], SCALE);
                float lo, hi;
                asm("mov.b64 {%0, %1}, %2;" : "=f"(lo), "=f"(hi) : "l"(r));
                *(float2*)(y + base + (size_t)(g * 32 + k) * PIX_PER_IMG)
                    = make_float2(lo, hi);
            }
        }
        // half B: outputs k = 16..31
        {
            uint64_t u[16];
            #pragma unroll
            for (int j = 0; j < 16; j++)
                u[j] = subx2(sr[(size_t)j * 8], sr[(size_t)(j + 16) * 8]);
            fwht16(u);
            #pragma unroll
            for (int k = 0; k < 16; k++) {
                uint64_t r = mulx2(u[k], SCALE);
                float lo, hi;
                asm("mov.b64 {%0, %1}, %2;" : "=f"(lo), "=f"(hi) : "l"(r));
                *(float2*)(y + base + (size_t)(g * 32 + 16 + k) * PIX_PER_IMG)
                    = make_float2(lo, hi);
            }
        }
    }
}

extern "C" void kernel_launch(void* const* d_in, const int* in_sizes, int n_in,
                              void* d_out, int out_size) {
    (void)in_sizes; (void)n_in; (void)out_size;
    const float* x = (const float*)d_in[0];
    float* y = (float*)d_out;

    const int smem_bytes = 792 * 8 * sizeof(uint64_t);   // 50688
    cudaFuncSetAttribute(fwht1024_kernel,
                         cudaFuncAttributeMaxDynamicSharedMemorySize, smem_bytes);

    const int grid = 16 * TILES_PER_IMG;   // 3136 tiles
    fwht1024_kernel<<<grid, THREADS, smem_bytes>>>(x, y);
}

// round 8
// speedup vs baseline: 1.7655x; 1.4840x over previous
#include <cuda_runtime.h>
#include <cstdint>

// HadamardTransform: y[b,:,h,w] = (H_1024 @ pad(x[b,:,h,w]))[0:768] / 32
// FWHT-1024 per pixel, packed f32x2 math (2 pixels per thread), two register
// passes (c_hi bits 5-9, then c_lo bits 0-4) with one smem transpose.
// TILE=8 pixels / 128 threads: same per-thread work as the 55.3us R5 kernel,
// but half the CTA granularity -> half the drain-tail quantum. 6 CTAs/SM.

#define DIMC          768
#define TILE          8           // pixels per CTA
#define THREADS       128
#define PIX_PER_IMG   3136        // 56*56
#define TILES_PER_IMG 392         // 3136/8

// ---- packed f32x2 ops (sm_103a) ----
__device__ __forceinline__ uint64_t addx2(uint64_t a, uint64_t b) {
    uint64_t d; asm("add.rn.f32x2 %0, %1, %2;" : "=l"(d) : "l"(a), "l"(b)); return d;
}
__device__ __forceinline__ uint64_t subx2(uint64_t a, uint64_t b) {
    const uint64_t NEG1 = 0xBF800000BF800000ULL;   // (-1.0f, -1.0f)
    uint64_t d; asm("fma.rn.f32x2 %0, %1, %2, %3;" : "=l"(d) : "l"(b), "l"(NEG1), "l"(a)); return d;
}
__device__ __forceinline__ uint64_t mulx2(uint64_t a, uint64_t b) {
    uint64_t d; asm("mul.rn.f32x2 %0, %1, %2;" : "=l"(d) : "l"(a), "l"(b)); return d;
}

// smem layout (u64 units): row r (0..767) at (r + (r>>5))*4 + p2.
// Conflict-free in both passes (verified: pass-1 covers 32 consecutive u64
// per phase; pass-2 lane bank = (8g + 2*p2) mod 32, distinct per phase).

__global__ __launch_bounds__(THREADS, 6)
void fwht1024_kernel(const float* __restrict__ x, float* __restrict__ y) {
    extern __shared__ uint64_t s[];   // 792*4 u64 = 25344 B

    const int tid = threadIdx.x;
    const int T   = blockIdx.x;
    const int b   = T / TILES_PER_IMG;
    const int p0  = (T % TILES_PER_IMG) * TILE;

    const int p2 = tid & 3;        // pixel pair -> pixels 2*p2, 2*p2+1
    const int g  = tid >> 2;       // 0..31

    const size_t base = (size_t)b * DIMC * PIX_PER_IMG + p0 + 2 * p2;

    // ---- Pass 1: butterfly over channel bits 5..9, gmem -> smem ----
    // Thread owns channels c = j*32 + g; j >= 24 are zero padding.
    {
        uint64_t w[32];
        #pragma unroll
        for (int j = 0; j < 24; j++) {
            const float2 v = *(const float2*)(x + base +
                               (size_t)(j * 32 + g) * PIX_PER_IMG);
            uint64_t u;
            asm("mov.b64 %0, {%1, %2};" : "=l"(u) : "f"(v.x), "f"(v.y));
            w[j] = u;
        }
        #pragma unroll
        for (int j = 24; j < 32; j++)
            w[j] = 0ULL;

        #pragma unroll
        for (int st = 0; st < 5; st++) {
            const int m = 1 << st;
            #pragma unroll
            for (int j = 0; j < 32; j++) {
                if (!(j & m)) {
                    uint64_t a = w[j], c2 = w[j + m];
                    w[j]     = addx2(a, c2);
                    w[j + m] = subx2(a, c2);
                }
            }
        }

        // only intermediates with j < 24 are ever read (outputs keep k < 768)
        #pragma unroll
        for (int j = 0; j < 24; j++)
            s[(j * 33 + g) * 4 + p2] = w[j];
    }
    __syncthreads();

    // ---- Pass 2: butterfly over channel bits 0..4, smem -> gmem ----
    if (g < 24) {
        uint64_t w[32];
        #pragma unroll
        for (int j = 0; j < 32; j++)
            w[j] = s[(g * 33 + j) * 4 + p2];

        #pragma unroll
        for (int st = 0; st < 5; st++) {
            const int m = 1 << st;
            #pragma unroll
            for (int j = 0; j < 32; j++) {
                if (!(j & m)) {
                    uint64_t a = w[j], c2 = w[j + m];
                    w[j]     = addx2(a, c2);
                    w[j + m] = subx2(a, c2);
                }
            }
        }

        const uint64_t SCALE = 0x3D0000003D000000ULL;   // (1/32, 1/32)
        #pragma unroll
        for (int j = 0; j < 32; j++) {
            uint64_t r = mulx2(w[j], SCALE);
            float lo, hi;
            asm("mov.b64 {%0, %1}, %2;" : "=f"(lo), "=f"(hi) : "l"(r));
            *(float2*)(y + base + (size_t)(g * 32 + j) * PIX_PER_IMG)
                = make_float2(lo, hi);
        }
    }
}

extern "C" void kernel_launch(void* const* d_in, const int* in_sizes, int n_in,
                              void* d_out, int out_size) {
    (void)in_sizes; (void)n_in; (void)out_size;
    const float* x = (const float*)d_in[0];
    float* y = (float*)d_out;

    const int smem_bytes = 792 * 4 * sizeof(uint64_t);   // 25344
    cudaFuncSetAttribute(fwht1024_kernel,
                         cudaFuncAttributeMaxDynamicSharedMemorySize, smem_bytes);

    const int grid = 16 * TILES_PER_IMG;   // 6272 tiles
    fwht1024_kernel<<<grid, THREADS, smem_bytes>>>(x, y);
}

// round 9
// speedup vs baseline: 2.0906x; 1.1842x over previous
#include <cuda_runtime.h>
#include <cstdint>

// HadamardTransform: y[b,:,h,w] = (H_1024 @ pad(x[b,:,h,w]))[0:768] / 32
// FWHT-1024 per pixel, two register passes over channel bits (5-9 then 0-4),
// packed f32x2 math (2 pixels per thread), 64-bit gmem/smem ops throughout.
// R5 structure (best known: 55.3us) + streaming cache hints on the
// single-touch global streams.

#define DIMC          768
#define TILE          16          // pixels per CTA
#define THREADS       256
#define PIX_PER_IMG   3136        // 56*56
#define TILES_PER_IMG 196         // 3136/16

// ---- packed f32x2 ops (sm_103a) ----
__device__ __forceinline__ uint64_t addx2(uint64_t a, uint64_t b) {
    uint64_t d; asm("add.rn.f32x2 %0, %1, %2;" : "=l"(d) : "l"(a), "l"(b)); return d;
}
__device__ __forceinline__ uint64_t subx2(uint64_t a, uint64_t b) {
    const uint64_t NEG1 = 0xBF800000BF800000ULL;   // (-1.0f, -1.0f)
    uint64_t d; asm("fma.rn.f32x2 %0, %1, %2, %3;" : "=l"(d) : "l"(b), "l"(NEG1), "l"(a)); return d;
}
__device__ __forceinline__ uint64_t mulx2(uint64_t a, uint64_t b) {
    uint64_t d; asm("mul.rn.f32x2 %0, %1, %2;" : "=l"(d) : "l"(a), "l"(b)); return d;
}

// smem layout (float2 units): row r (0..767) at (r + (r>>5))*8 + p2.
// Conflict-free 64-bit LDS/STS phases in both passes
// (32-row stride = 528 words == 16 mod 32).

__global__ __launch_bounds__(THREADS, 3)
void fwht1024_kernel(const float* __restrict__ x, float* __restrict__ y) {
    extern __shared__ uint64_t s[];   // 792*8 = 6336 u64 = 50688 B

    const int tid = threadIdx.x;
    const int T   = blockIdx.x;
    const int b   = T / TILES_PER_IMG;
    const int p0  = (T % TILES_PER_IMG) * TILE;

    const int p2 = tid & 7;        // pixel pair -> pixels 2*p2, 2*p2+1
    const int g  = tid >> 3;       // 0..31

    const size_t base = (size_t)b * DIMC * PIX_PER_IMG + p0 + 2 * p2;

    // ---- Pass 1: butterfly over channel bits 5..9, gmem -> smem ----
    // Thread owns channels c = j*32 + g; j >= 24 are zero padding.
    {
        uint64_t w[32];
        #pragma unroll
        for (int j = 0; j < 24; j++) {
            const float2 v = __ldcs((const float2*)(x + base +
                               (size_t)(j * 32 + g) * PIX_PER_IMG));
            uint64_t u;
            asm("mov.b64 %0, {%1, %2};" : "=l"(u) : "f"(v.x), "f"(v.y));
            w[j] = u;
        }
        #pragma unroll
        for (int j = 24; j < 32; j++)
            w[j] = 0ULL;

        #pragma unroll
        for (int st = 0; st < 5; st++) {
            const int m = 1 << st;
            #pragma unroll
            for (int j = 0; j < 32; j++) {
                if (!(j & m)) {
                    uint64_t a = w[j], c2 = w[j + m];
                    w[j]     = addx2(a, c2);
                    w[j + m] = subx2(a, c2);
                }
            }
        }

        // only intermediates with j < 24 are ever read (outputs keep k < 768)
        #pragma unroll
        for (int j = 0; j < 24; j++)
            s[(j * 33 + g) * 8 + p2] = w[j];
    }
    __syncthreads();

    // ---- Pass 2: butterfly over channel bits 0..4, smem -> gmem ----
    if (g < 24) {
        uint64_t w[32];
        #pragma unroll
        for (int j = 0; j < 32; j++)
            w[j] = s[(g * 33 + j) * 8 + p2];

        #pragma unroll
        for (int st = 0; st < 5; st++) {
            const int m = 1 << st;
            #pragma unroll
            for (int j = 0; j < 32; j++) {
                if (!(j & m)) {
                    uint64_t a = w[j], c2 = w[j + m];
                    w[j]     = addx2(a, c2);
                    w[j + m] = subx2(a, c2);
                }
            }
        }

        const uint64_t SCALE = 0x3D0000003D000000ULL;   // (1/32, 1/32)
        #pragma unroll
        for (int j = 0; j < 32; j++) {
            uint64_t r = mulx2(w[j], SCALE);
            float lo, hi;
            asm("mov.b64 {%0, %1}, %2;" : "=f"(lo), "=f"(hi) : "l"(r));
            __stcs((float2*)(y + base + (size_t)(g * 32 + j) * PIX_PER_IMG),
                   make_float2(lo, hi));
        }
    }
}

extern "C" void kernel_launch(void* const* d_in, const int* in_sizes, int n_in,
                              void* d_out, int out_size) {
    (void)in_sizes; (void)n_in; (void)out_size;
    const float* x = (const float*)d_in[0];
    float* y = (float*)d_out;

    const int smem_bytes = 792 * 8 * sizeof(uint64_t);   // 50688
    cudaFuncSetAttribute(fwht1024_kernel,
                         cudaFuncAttributeMaxDynamicSharedMemorySize, smem_bytes);

    const int grid = 16 * TILES_PER_IMG;   // 3136 tiles
    fwht1024_kernel<<<grid, THREADS, smem_bytes>>>(x, y);
}